// round 5
// baseline (speedup 1.0000x reference)
#include <cuda_runtime.h>

#define NMAX 100000

// ---------------- scratch (device globals; no allocations) ----------------
__device__ float g_cref[4][NMAX];           // per-branch c_ref = refp . att[:64]
__device__ float g_l1[4][NMAX];             // per-branch L1(refp)
__device__ float g_E[4][(size_t)NMAX * 64]; // e_attr0, e_rel0, e_attr1, e_rel1
__device__ float g_E0[(size_t)NMAX * 64];   // elu-combined relation-0 embedding
__device__ float g_E1[(size_t)NMAX * 64];   // elu-combined relation-1 embedding
__device__ float g_acc[7 * 64];             // tanh-GEMV column sums: 0-3 agg, 4 e0, 5 e1, 6 tf
__device__ float g_beta[8];                 // 0-3: intra betas, 4-6: inter betas

// ---------------- helpers ----------------
static __device__ __forceinline__ float2 ffma2(float2 a, float2 b, float2 c) {
    float2 d;
    asm("fma.rn.f32x2 %0, %1, %2, %3;"
        : "=l"(reinterpret_cast<unsigned long long &>(d))
        : "l"(reinterpret_cast<unsigned long long &>(a)),
          "l"(reinterpret_cast<unsigned long long &>(b)),
          "l"(reinterpret_cast<unsigned long long &>(c)));
    return d;
}

static __device__ __forceinline__ float2 wred2(float2 v) {
#pragma unroll
    for (int m = 16; m > 0; m >>= 1) {
        v.x += __shfl_xor_sync(0xffffffffu, v.x, m);
        v.y += __shfl_xor_sync(0xffffffffu, v.y, m);
    }
    return v;
}

static __device__ __forceinline__ float wredf(float v) {
#pragma unroll
    for (int m = 16; m > 0; m >>= 1) v += __shfl_xor_sync(0xffffffffu, v, m);
    return v;
}

static __device__ __forceinline__ float eluf(float x) { return x > 0.f ? x : expm1f(x); }

// Load W[64][64] (row major; out[j] = sum_k x[k]*W[j][k]) into smem as
// float2 ws[l*66 + k] = (W[2l][k], W[2l+1][k]); row stride 66 avoids conflicts.
static __device__ __forceinline__ void load_wt(float2 *ws, const float *__restrict__ W,
                                               int tid, int nthreads) {
    for (int idx = tid; idx < 4096; idx += nthreads) {
        int j = idx >> 6, k = idx & 63;
        ((float *)ws)[((((j >> 1) * 66) + k) << 1) | (j & 1)] = W[idx];
    }
}

// 64x64 GEMV for one node held by one warp: lane l produces out[2l], out[2l+1].
static __device__ __forceinline__ float2 gemv64(const float2 *__restrict__ ws,
                                                float2 *dupw, float2 x2, float2 bias, int l) {
    dupw[2 * l] = make_float2(x2.x, x2.x);
    dupw[2 * l + 1] = make_float2(x2.y, x2.y);
    __syncwarp();
    float2 a0 = bias, a1 = make_float2(0.f, 0.f);
#pragma unroll
    for (int k = 0; k < 64; k += 2) {
        float4 r = *(const float4 *)(dupw + k);
        float4 w = *(const float4 *)(ws + l * 66 + k);
        a0 = ffma2(make_float2(r.x, r.y), make_float2(w.x, w.y), a0);
        a1 = ffma2(make_float2(r.z, r.w), make_float2(w.z, w.w), a1);
    }
    __syncwarp();
    return make_float2(a0.x + a1.x, a0.y + a1.y);
}

// ---------------- kernels ----------------
__global__ void init_kernel() {
    int t = threadIdx.x;
    if (t < 7 * 64) g_acc[t] = 0.f;
}

// For one input matrix x [n,64] and two weight sets, compute c_ref and L1(refp)
// per node for branch slots c0 and c1 (refp itself never stored).
__global__ void __launch_bounds__(256) prep_kernel(
    const float *__restrict__ x,
    const float *__restrict__ W0, const float *__restrict__ b0, const float *__restrict__ att0_,
    const float *__restrict__ W1, const float *__restrict__ b1, const float *__restrict__ att1_,
    int c0, int c1, int n) {
    __shared__ __align__(16) float2 ws0[32 * 66];
    __shared__ __align__(16) float2 ws1[32 * 66];
    __shared__ __align__(16) float2 dup[8][64];
    int tid = threadIdx.x, w = tid >> 5, l = tid & 31;
    load_wt(ws0, W0, tid, 256);
    load_wt(ws1, W1, tid, 256);
    __syncthreads();
    float2 bb0 = __ldg((const float2 *)b0 + l);
    float2 bb1 = __ldg((const float2 *)b1 + l);
    float2 aa0 = __ldg((const float2 *)att0_ + l);  // first half of att vector
    float2 aa1 = __ldg((const float2 *)att1_ + l);
    float2 *dupw = dup[w];
    for (int node = blockIdx.x * 8 + w; node < n; node += gridDim.x * 8) {
        float2 x2 = __ldg((const float2 *)(x + (size_t)node * 64) + l);
        dupw[2 * l] = make_float2(x2.x, x2.x);
        dupw[2 * l + 1] = make_float2(x2.y, x2.y);
        __syncwarp();
        float2 p0 = bb0, p0b = make_float2(0.f, 0.f);
        float2 p1 = bb1, p1b = make_float2(0.f, 0.f);
#pragma unroll
        for (int k = 0; k < 64; k += 2) {
            float4 r = *(const float4 *)(dupw + k);
            float4 wA = *(const float4 *)(ws0 + l * 66 + k);
            float4 wB = *(const float4 *)(ws1 + l * 66 + k);
            p0 = ffma2(make_float2(r.x, r.y), make_float2(wA.x, wA.y), p0);
            p0b = ffma2(make_float2(r.z, r.w), make_float2(wA.z, wA.w), p0b);
            p1 = ffma2(make_float2(r.x, r.y), make_float2(wB.x, wB.y), p1);
            p1b = ffma2(make_float2(r.z, r.w), make_float2(wB.z, wB.w), p1b);
        }
        __syncwarp();
        float2 r0 = make_float2(p0.x + p0b.x, p0.y + p0b.y);
        float2 r1 = make_float2(p1.x + p1b.x, p1.y + p1b.y);
        float2 q0 = wred2(make_float2(r0.x * aa0.x + r0.y * aa0.y, fabsf(r0.x) + fabsf(r0.y)));
        float2 q1 = wred2(make_float2(r1.x * aa1.x + r1.y * aa1.y, fabsf(r1.x) + fabsf(r1.y)));
        if (l == 0) {
            g_cref[c0][node] = q0.x; g_l1[c0][node] = q0.y;
            g_cref[c1][node] = q1.x; g_l1[c1][node] = q1.y;
        }
    }
}

static __device__ __forceinline__ void do_branch(const float *__restrict__ tab,
                                                 const int *idx, float2 a2,
                                                 float cref, float l1ref,
                                                 float *__restrict__ eout, int l) {
    float2 v[8];
    float sc[8];
#pragma unroll
    for (int s = 0; s < 8; s++)
        v[s] = __ldg((const float2 *)(tab + (size_t)idx[s] * 64) + l);
#pragma unroll
    for (int s = 0; s < 8; s++) {
        float2 p;
        p.x = v[s].x * a2.x + v[s].y * a2.y;  // partial dot with att[64:]
        p.y = fabsf(v[s].x) + fabsf(v[s].y);  // partial L1
        p = wred2(p);
        float t = __fdividef(cref + p.x, fmaxf(l1ref + p.y, 1e-12f));
        sc[s] = t > 0.f ? t : 0.01f * t;      // leaky_relu 0.01
    }
    float mx = sc[0];
#pragma unroll
    for (int s = 1; s < 8; s++) mx = fmaxf(mx, sc[s]);
    float sum = 0.f;
#pragma unroll
    for (int s = 0; s < 8; s++) { sc[s] = __expf(sc[s] - mx); sum += sc[s]; }
    float inv = __fdividef(1.f, sum);
    float2 o = make_float2(0.f, 0.f);
#pragma unroll
    for (int s = 0; s < 8; s++) {
        float ww = sc[s] * inv;
        o.x = fmaf(ww, v[s].x, o.x);
        o.y = fmaf(ww, v[s].y, o.y);
    }
    *((float2 *)eout + l) = o;
}

__global__ void __launch_bounds__(256) attn_kernel(
    const float *__restrict__ tab, const float *__restrict__ rtab,
    const int *__restrict__ nei,
    const float *__restrict__ attA, const float *__restrict__ attR, int cidx, int n) {
    int tid = threadIdx.x, w = tid >> 5, l = tid & 31;
    int node = blockIdx.x * 8 + w;
    if (node >= n) return;
    float2 aA = __ldg((const float2 *)(attA + 64) + l);  // second half of att
    float2 aR = __ldg((const float2 *)(attR + 64) + l);
    const int4 *np = (const int4 *)(nei + (size_t)node * 8);
    int4 i0 = __ldg(np), i1 = __ldg(np + 1);
    int idx[8] = {i0.x, i0.y, i0.z, i0.w, i1.x, i1.y, i1.z, i1.w};
    do_branch(tab, idx, aA, g_cref[cidx][node], g_l1[cidx][node],
              &g_E[cidx][(size_t)node * 64], l);
    do_branch(rtab, idx, aR, g_cref[cidx + 1][node], g_l1[cidx + 1][node],
              &g_E[cidx + 1][(size_t)node * 64], l);
}

// column sums of tanh(x @ W^T + b) over all nodes -> g_acc[acc_idx*64 ..]
__global__ void __launch_bounds__(256) gemv_tanh_sum(
    const float *__restrict__ xptr, int e_idx,
    const float *__restrict__ W, const float *__restrict__ bias, int acc_idx, int n) {
    __shared__ __align__(16) float2 ws[32 * 66];
    __shared__ __align__(16) float2 dup[8][64];
    __shared__ float2 red[8][32];
    int tid = threadIdx.x, w = tid >> 5, l = tid & 31;
    const float *x = xptr;
    if (e_idx >= 0) {
        if (e_idx < 4) x = g_E[e_idx];
        else if (e_idx == 4) x = g_E0;
        else x = g_E1;
    }
    load_wt(ws, W, tid, 256);
    __syncthreads();
    float2 bb = __ldg((const float2 *)bias + l);
    float2 acc = make_float2(0.f, 0.f);
    float2 *dupw = dup[w];
    for (int node = blockIdx.x * 8 + w; node < n; node += gridDim.x * 8) {
        float2 x2 = *((const float2 *)(x + (size_t)node * 64) + l);
        float2 t = gemv64(ws, dupw, x2, bb, l);
        acc.x += tanhf(t.x);
        acc.y += tanhf(t.y);
    }
    red[w][l] = acc;
    __syncthreads();
    if (w == 0) {
        float2 s = red[0][l];
#pragma unroll
        for (int ww = 1; ww < 8; ww++) { s.x += red[ww][l].x; s.y += red[ww][l].y; }
        atomicAdd(&g_acc[acc_idx * 64 + 2 * l], s.x);
        atomicAdd(&g_acc[acc_idx * 64 + 2 * l + 1], s.y);
    }
}

// per-relation semantic-attention beta (2-way softmax)
__global__ void beta_rel_kernel(const float *__restrict__ agg0,
                                const float *__restrict__ agg1, int n) {
    int tid = threadIdx.x;
    int r = tid >> 5, l = tid & 31;
    if (r > 1) return;
    const float *aat = r ? agg1 : agg0;
    float invN = 1.f / (float)n;
    float2 at = __ldg((const float2 *)aat + l);
    const float *accA = g_acc + (2 * r) * 64;
    const float *accB = g_acc + (2 * r + 1) * 64;
    float pa = (accA[2 * l] * invN) * at.x + (accA[2 * l + 1] * invN) * at.y;
    float pb = (accB[2 * l] * invN) * at.x + (accB[2 * l + 1] * invN) * at.y;
    float2 q = wred2(make_float2(pa, pb));
    if (l == 0) {
        float m = fmaxf(q.x, q.y);
        float ea = expf(q.x - m), eb = expf(q.y - m);
        float inv = 1.f / (ea + eb);
        g_beta[2 * r] = ea * inv;
        g_beta[2 * r + 1] = eb * inv;
    }
}

__global__ void combine_kernel(int n) {
    int i = blockIdx.x * blockDim.x + threadIdx.x;
    if (i >= n * 32) return;
    float b00 = g_beta[0], b01 = g_beta[1], b10 = g_beta[2], b11 = g_beta[3];
    float2 ea = ((const float2 *)g_E[0])[i];
    float2 er = ((const float2 *)g_E[1])[i];
    float2 fa = ((const float2 *)g_E[2])[i];
    float2 fr = ((const float2 *)g_E[3])[i];
    float2 c0, c1;
    c0.x = eluf(b00 * ea.x + b01 * er.x);
    c0.y = eluf(b00 * ea.y + b01 * er.y);
    c1.x = eluf(b10 * fa.x + b11 * fr.x);
    c1.y = eluf(b10 * fa.y + b11 * fr.y);
    ((float2 *)g_E0)[i] = c0;
    ((float2 *)g_E1)[i] = c1;
}

__global__ void beta_inter_kernel(const float *__restrict__ interatt, int n) {
    int l = threadIdx.x;
    float invN = 1.f / (float)n;
    float2 at = __ldg((const float2 *)interatt + l);
    float p[3];
#pragma unroll
    for (int k = 0; k < 3; k++) {
        float px = (g_acc[(4 + k) * 64 + 2 * l] * invN) * at.x +
                   (g_acc[(4 + k) * 64 + 2 * l + 1] * invN) * at.y;
        p[k] = wredf(px);
    }
    if (l == 0) {
        float m = fmaxf(p[0], fmaxf(p[1], p[2]));
        float e0 = expf(p[0] - m), e1 = expf(p[1] - m), e2 = expf(p[2] - m);
        float inv = 1.f / (e0 + e1 + e2);
        g_beta[4] = e0 * inv;
        g_beta[5] = e1 * inv;
        g_beta[6] = e2 * inv;
    }
}

__global__ void final_kernel(const float *__restrict__ tf, float *__restrict__ out, int n) {
    int i = blockIdx.x * blockDim.x + threadIdx.x;
    if (i >= n * 32) return;
    float b0 = g_beta[4], b1 = g_beta[5], b2 = g_beta[6];
    float2 e0 = ((const float2 *)g_E0)[i];
    float2 e1 = ((const float2 *)g_E1)[i];
    float2 t = ((const float2 *)tf)[i];
    float2 o;
    o.x = b0 * e0.x + b1 * e1.x + b2 * t.x;
    o.y = b0 * e0.y + b1 * e1.y + b2 * t.y;
    ((float2 *)out)[i] = o;
}

// ---------------- launch ----------------
extern "C" void kernel_launch(void *const *d_in, const int *in_sizes, int n_in,
                              void *d_out, int out_size) {
    const float *tf = (const float *)d_in[0];
    const float *h0 = (const float *)d_in[1];
    const float *h1 = (const float *)d_in[2];
    const float *h2 = (const float *)d_in[3];
    const float *rf0 = (const float *)d_in[4];
    const float *rf1 = (const float *)d_in[5];
    const float *rf2 = (const float *)d_in[6];
    const int *nei0 = (const int *)d_in[7];
    const int *nei1 = (const int *)d_in[8];
    const float *att0 = (const float *)d_in[9];
    const float *att2_0 = (const float *)d_in[10];
    const float *Wr0 = (const float *)d_in[11];
    const float *br0 = (const float *)d_in[12];
    const float *Wr2_0 = (const float *)d_in[13];
    const float *br2_0 = (const float *)d_in[14];
    const float *aggW0 = (const float *)d_in[15];
    const float *aggb0 = (const float *)d_in[16];
    const float *aggatt0 = (const float *)d_in[17];
    const float *att1 = (const float *)d_in[18];
    const float *att2_1 = (const float *)d_in[19];
    const float *Wr1 = (const float *)d_in[20];
    const float *br1 = (const float *)d_in[21];
    const float *Wr2_1 = (const float *)d_in[22];
    const float *br2_1 = (const float *)d_in[23];
    const float *aggW1 = (const float *)d_in[24];
    const float *aggb1 = (const float *)d_in[25];
    const float *aggatt1 = (const float *)d_in[26];
    const float *interW = (const float *)d_in[27];
    const float *interb = (const float *)d_in[28];
    const float *interatt = (const float *)d_in[29];

    int n = in_sizes[0] / 64;
    if (n > NMAX) n = NMAX;
    float *out = (float *)d_out;

    init_kernel<<<1, 512>>>();

    // prep: c_ref / L1(refp) for the 4 branches (2 launches; each input shared
    // by the two relations' weight sets)
    prep_kernel<<<448, 256>>>(h0, Wr0, br0, att0, Wr1, br1, att1, 0, 2, n);
    prep_kernel<<<448, 256>>>(rf0, Wr2_0, br2_0, att2_0, Wr2_1, br2_1, att2_1, 1, 3, n);

    int ablocks = (n + 7) / 8;
    attn_kernel<<<ablocks, 256>>>(h1, rf1, nei0, att0, att2_0, 0, n);
    attn_kernel<<<ablocks, 256>>>(h2, rf2, nei1, att1, att2_1, 2, n);

    // semantic-agg tanh column sums (4 branches) + inter tanh sum of target
    gemv_tanh_sum<<<448, 256>>>(nullptr, 0, aggW0, aggb0, 0, n);
    gemv_tanh_sum<<<448, 256>>>(nullptr, 1, aggW0, aggb0, 1, n);
    gemv_tanh_sum<<<448, 256>>>(nullptr, 2, aggW1, aggb1, 2, n);
    gemv_tanh_sum<<<448, 256>>>(nullptr, 3, aggW1, aggb1, 3, n);
    gemv_tanh_sum<<<448, 256>>>(tf, -1, interW, interb, 6, n);

    beta_rel_kernel<<<1, 64>>>(aggatt0, aggatt1, n);

    int eblocks = (n * 32 + 255) / 256;
    combine_kernel<<<eblocks, 256>>>(n);

    // inter tanh column sums for the two combined embeddings
    gemv_tanh_sum<<<448, 256>>>(nullptr, 4, interW, interb, 4, n);
    gemv_tanh_sum<<<448, 256>>>(nullptr, 5, interW, interb, 5, n);

    beta_inter_kernel<<<1, 32>>>(interatt, n);

    final_kernel<<<eblocks, 256>>>(tf, out, n);
}

// round 6
// speedup vs baseline: 1.3783x; 1.3783x over previous
#include <cuda_runtime.h>

#define NMAX 100000
#define M1MAX 200000
#define M2MAX 100000

// ---------------- scratch (device globals; no allocations) ----------------
__device__ float g_cref[4][NMAX];           // per-branch c_ref = refp . att[:64]
__device__ float g_l1[4][NMAX];             // per-branch L1(refp)
__device__ float g_E[4][(size_t)NMAX * 64]; // e_attr0, e_rel0, e_attr1, e_rel1
__device__ float g_E0[(size_t)NMAX * 64];   // elu-combined relation-0 embedding
__device__ float g_E1[(size_t)NMAX * 64];   // elu-combined relation-1 embedding
__device__ float g_acc[7 * 64];             // tanh-GEMV column sums
__device__ float g_beta[8];                 // 0-3 intra betas, 4-6 inter betas
// per-table-row precomputed (dot with att[64:], L1):
__device__ float2 g_cd_t1[M1MAX];           // h1
__device__ float2 g_cd_r1[M1MAX];           // rf1
__device__ float2 g_cd_t2[M2MAX];           // h2
__device__ float2 g_cd_r2[M2MAX];           // rf2

// ---------------- helpers ----------------
static __device__ __forceinline__ float2 ffma2(float2 a, float2 b, float2 c) {
    float2 d;
    asm("fma.rn.f32x2 %0, %1, %2, %3;"
        : "=l"(reinterpret_cast<unsigned long long &>(d))
        : "l"(reinterpret_cast<unsigned long long &>(a)),
          "l"(reinterpret_cast<unsigned long long &>(b)),
          "l"(reinterpret_cast<unsigned long long &>(c)));
    return d;
}

static __device__ __forceinline__ float2 wred2(float2 v) {
#pragma unroll
    for (int m = 16; m > 0; m >>= 1) {
        v.x += __shfl_xor_sync(0xffffffffu, v.x, m);
        v.y += __shfl_xor_sync(0xffffffffu, v.y, m);
    }
    return v;
}

static __device__ __forceinline__ float wredf(float v) {
#pragma unroll
    for (int m = 16; m > 0; m >>= 1) v += __shfl_xor_sync(0xffffffffu, v, m);
    return v;
}

static __device__ __forceinline__ float eluf(float x) { return x > 0.f ? x : expm1f(x); }

// fast tanh: clamped (e^(2x)-1)/(e^(2x)+1); abs err ~1e-7
static __device__ __forceinline__ float ftanh(float x) {
    float cx = fminf(fmaxf(x, -12.f), 12.f);
    float e = __expf(2.f * cx);
    return __fdividef(e - 1.f, e + 1.f);
}

extern __shared__ float smem_dyn[];

// ---------------- kernels ----------------
__global__ void init_kernel() {
    int t = threadIdx.x;
    if (t < 7 * 64) g_acc[t] = 0.f;
}

// Per-table-row precompute: out[row] = (row . att2, L1(row)) for two tables.
__global__ void __launch_bounds__(256) precomp_kernel(
    const float *__restrict__ tab, const float *__restrict__ rtab,
    float2 *__restrict__ outT, float2 *__restrict__ outR,
    const float *__restrict__ attT2, const float *__restrict__ attR2, int m) {
    int w = threadIdx.x >> 5, l = threadIdx.x & 31;
    float2 aT = __ldg((const float2 *)attT2 + l);
    float2 aR = __ldg((const float2 *)attR2 + l);
    int row = blockIdx.x * 8 + w;
    if (row >= m) return;
    float2 v = __ldg((const float2 *)(tab + (size_t)row * 64) + l);
    float2 q = wred2(make_float2(v.x * aT.x + v.y * aT.y, fabsf(v.x) + fabsf(v.y)));
    float2 u = __ldg((const float2 *)(rtab + (size_t)row * 64) + l);
    float2 p = wred2(make_float2(u.x * aR.x + u.y * aR.y, fabsf(u.x) + fabsf(u.y)));
    if (l == 0) { outT[row] = q; outR[row] = p; }
}

// Thread-per-node dual 64x64 GEMV: c_ref / L1(refp) for branch slots c0, c1.
// dyn smem: ws0[4096], ws1[4096], par[256]={b0,b1,att0h,att1h}, xs[256*68]
#define PREP_SMEM_F (4096 * 2 + 256 + 256 * 68)
__global__ void __launch_bounds__(256) prep_v2(
    const float *__restrict__ x,
    const float *__restrict__ W0, const float *__restrict__ b0, const float *__restrict__ att0,
    const float *__restrict__ W1, const float *__restrict__ b1, const float *__restrict__ att1,
    int c0, int c1, int n) {
    float *ws0 = smem_dyn;
    float *ws1 = smem_dyn + 4096;
    float *par = smem_dyn + 8192;
    float *xs = smem_dyn + 8448;
    int tid = threadIdx.x;
    for (int i = tid; i < 4096; i += 256) { ws0[i] = W0[i]; ws1[i] = W1[i]; }
    if (tid < 64) {
        par[tid] = b0[tid]; par[64 + tid] = b1[tid];
        par[128 + tid] = att0[tid]; par[192 + tid] = att1[tid];
    }
    int tile = blockIdx.x * 256;
    int rows = n - tile; if (rows > 256) rows = 256;
    const float4 *xg = (const float4 *)(x + (size_t)tile * 64);
    for (int i = tid; i < rows * 16; i += 256)
        *(float4 *)&xs[(i >> 4) * 68 + (i & 15) * 4] = xg[i];
    __syncthreads();
    if (tid >= rows) return;
    int me = tile + tid;
    float4 xr[16];
#pragma unroll
    for (int k = 0; k < 16; k++) xr[k] = *(const float4 *)&xs[tid * 68 + k * 4];
    float cr0 = 0.f, l10 = 0.f, cr1 = 0.f, l11 = 0.f;
#pragma unroll 2
    for (int j = 0; j < 64; j++) {
        const float4 *w0 = (const float4 *)&ws0[j * 64];
        const float4 *w1 = (const float4 *)&ws1[j * 64];
        float2 a0 = make_float2(0.f, 0.f), a1 = a0, c0v = a0, c1v = a0;
#pragma unroll
        for (int k = 0; k < 16; k++) {
            float4 xk = xr[k];
            float4 w = w0[k];
            a0 = ffma2(make_float2(xk.x, xk.y), make_float2(w.x, w.y), a0);
            a1 = ffma2(make_float2(xk.z, xk.w), make_float2(w.z, w.w), a1);
            float4 v = w1[k];
            c0v = ffma2(make_float2(xk.x, xk.y), make_float2(v.x, v.y), c0v);
            c1v = ffma2(make_float2(xk.z, xk.w), make_float2(v.z, v.w), c1v);
        }
        float r0 = (a0.x + a1.x) + (a0.y + a1.y) + par[j];
        float r1 = (c0v.x + c1v.x) + (c0v.y + c1v.y) + par[64 + j];
        cr0 = fmaf(r0, par[128 + j], cr0); l10 += fabsf(r0);
        cr1 = fmaf(r1, par[192 + j], cr1); l11 += fabsf(r1);
    }
    g_cref[c0][me] = cr0; g_l1[c0][me] = l10;
    g_cref[c1][me] = cr1; g_l1[c1][me] = l11;
}

// Thread-per-node GEMV + tanh + column-sum into g_acc[acc_idx*64..].
// dyn smem: ws[4096], bs[64], xs[256*68] (xs reused for block reduction)
#define GEMV_SMEM_F (4096 + 64 + 256 * 68)
__global__ void __launch_bounds__(256) gemv_tanh_sum_v2(
    const float *xptr, int e_idx,
    const float *__restrict__ W, const float *__restrict__ bias, int acc_idx, int n) {
    float *ws = smem_dyn;
    float *bs = smem_dyn + 4096;
    float *xs = smem_dyn + 4160;
    int tid = threadIdx.x, w = tid >> 5, lid = tid & 31;
    const float *x = xptr;
    if (e_idx >= 0) {
        if (e_idx < 4) x = g_E[e_idx];
        else if (e_idx == 4) x = g_E0;
        else x = g_E1;
    }
    for (int i = tid; i < 4096; i += 256) ws[i] = W[i];
    if (tid < 64) bs[tid] = bias[tid];
    int tile = blockIdx.x * 256;
    int rows = n - tile; if (rows > 256) rows = 256;
    const float4 *xg = (const float4 *)(x + (size_t)tile * 64);
    for (int i = tid; i < rows * 16; i += 256)
        *(float4 *)&xs[(i >> 4) * 68 + (i & 15) * 4] = xg[i];
    __syncthreads();
    float4 xr[16];
#pragma unroll
    for (int k = 0; k < 16; k++) xr[k] = *(const float4 *)&xs[tid * 68 + k * 4];
    bool act = (tid < rows);
    float cs0 = 0.f, cs1 = 0.f;
#pragma unroll 2
    for (int j = 0; j < 64; j++) {
        const float4 *wr = (const float4 *)&ws[j * 64];
        float2 a0 = make_float2(0.f, 0.f), a1 = a0;
#pragma unroll
        for (int k = 0; k < 16; k++) {
            float4 xk = xr[k];
            float4 wv = wr[k];
            a0 = ffma2(make_float2(xk.x, xk.y), make_float2(wv.x, wv.y), a0);
            a1 = ffma2(make_float2(xk.z, xk.w), make_float2(wv.z, wv.w), a1);
        }
        float r = (a0.x + a1.x) + (a0.y + a1.y) + bs[j];
        float t = act ? ftanh(r) : 0.f;
        t = wredf(t);
        if (lid == (j & 31)) { if (j < 32) cs0 += t; else cs1 += t; }
    }
    // block reduce (reuse xs; all xr reads are done)
    __syncthreads();
    xs[w * 64 + lid] = cs0;
    xs[512 + w * 64 + lid] = cs1;
    __syncthreads();
    if (w == 0) {
        float s0 = 0.f, s1 = 0.f;
#pragma unroll
        for (int ww = 0; ww < 8; ww++) {
            s0 += xs[ww * 64 + lid];
            s1 += xs[512 + ww * 64 + lid];
        }
        atomicAdd(&g_acc[acc_idx * 64 + lid], s0);
        atomicAdd(&g_acc[acc_idx * 64 + 32 + lid], s1);
    }
}

static __device__ __forceinline__ void do_branch_v2(
    const float *__restrict__ tab, const float2 *__restrict__ cdl1,
    const int *idx, float cref, float l1ref, float *__restrict__ eout, int l) {
    float2 v[8];
    float sc[8];
#pragma unroll
    for (int s = 0; s < 8; s++)
        v[s] = __ldg((const float2 *)(tab + (size_t)idx[s] * 64) + l);
#pragma unroll
    for (int s = 0; s < 8; s++) {
        float2 cd = __ldg(cdl1 + idx[s]);  // uniform across lanes
        float t = __fdividef(cref + cd.x, fmaxf(l1ref + cd.y, 1e-12f));
        sc[s] = t > 0.f ? t : 0.01f * t;   // leaky_relu 0.01
    }
    float mx = sc[0];
#pragma unroll
    for (int s = 1; s < 8; s++) mx = fmaxf(mx, sc[s]);
    float sum = 0.f;
#pragma unroll
    for (int s = 0; s < 8; s++) { sc[s] = __expf(sc[s] - mx); sum += sc[s]; }
    float inv = __fdividef(1.f, sum);
    float2 o = make_float2(0.f, 0.f);
#pragma unroll
    for (int s = 0; s < 8; s++) {
        float ww = sc[s] * inv;
        o.x = fmaf(ww, v[s].x, o.x);
        o.y = fmaf(ww, v[s].y, o.y);
    }
    *((float2 *)eout + l) = o;
}

__global__ void __launch_bounds__(256) attn_v2(
    const float *__restrict__ tab, const float *__restrict__ rtab,
    const int *__restrict__ nei,
    const float2 *__restrict__ cdA, const float2 *__restrict__ cdR, int cidx, int n) {
    int tid = threadIdx.x, w = tid >> 5, l = tid & 31;
    int node = blockIdx.x * 8 + w;
    if (node >= n) return;
    const int4 *np = (const int4 *)(nei + (size_t)node * 8);
    int4 i0 = __ldg(np), i1 = __ldg(np + 1);
    int idx[8] = {i0.x, i0.y, i0.z, i0.w, i1.x, i1.y, i1.z, i1.w};
    do_branch_v2(tab, cdA, idx, g_cref[cidx][node], g_l1[cidx][node],
                 &g_E[cidx][(size_t)node * 64], l);
    do_branch_v2(rtab, cdR, idx, g_cref[cidx + 1][node], g_l1[cidx + 1][node],
                 &g_E[cidx + 1][(size_t)node * 64], l);
}

// per-relation semantic-attention beta (2-way softmax)
__global__ void beta_rel_kernel(const float *__restrict__ agg0,
                                const float *__restrict__ agg1, int n) {
    int tid = threadIdx.x;
    int r = tid >> 5, l = tid & 31;
    if (r > 1) return;
    const float *aat = r ? agg1 : agg0;
    float invN = 1.f / (float)n;
    float2 at = __ldg((const float2 *)aat + l);
    const float *accA = g_acc + (2 * r) * 64;
    const float *accB = g_acc + (2 * r + 1) * 64;
    float pa = (accA[2 * l] * invN) * at.x + (accA[2 * l + 1] * invN) * at.y;
    float pb = (accB[2 * l] * invN) * at.x + (accB[2 * l + 1] * invN) * at.y;
    float2 q = wred2(make_float2(pa, pb));
    if (l == 0) {
        float m = fmaxf(q.x, q.y);
        float ea = expf(q.x - m), eb = expf(q.y - m);
        float inv = 1.f / (ea + eb);
        g_beta[2 * r] = ea * inv;
        g_beta[2 * r + 1] = eb * inv;
    }
}

__global__ void combine_kernel(int n) {
    int i = blockIdx.x * blockDim.x + threadIdx.x;
    if (i >= n * 32) return;
    float b00 = g_beta[0], b01 = g_beta[1], b10 = g_beta[2], b11 = g_beta[3];
    float2 ea = ((const float2 *)g_E[0])[i];
    float2 er = ((const float2 *)g_E[1])[i];
    float2 fa = ((const float2 *)g_E[2])[i];
    float2 fr = ((const float2 *)g_E[3])[i];
    float2 c0, c1;
    c0.x = eluf(b00 * ea.x + b01 * er.x);
    c0.y = eluf(b00 * ea.y + b01 * er.y);
    c1.x = eluf(b10 * fa.x + b11 * fr.x);
    c1.y = eluf(b10 * fa.y + b11 * fr.y);
    ((float2 *)g_E0)[i] = c0;
    ((float2 *)g_E1)[i] = c1;
}

__global__ void beta_inter_kernel(const float *__restrict__ interatt, int n) {
    int l = threadIdx.x;
    float invN = 1.f / (float)n;
    float2 at = __ldg((const float2 *)interatt + l);
    float p[3];
#pragma unroll
    for (int k = 0; k < 3; k++) {
        float px = (g_acc[(4 + k) * 64 + 2 * l] * invN) * at.x +
                   (g_acc[(4 + k) * 64 + 2 * l + 1] * invN) * at.y;
        p[k] = wredf(px);
    }
    if (l == 0) {
        float m = fmaxf(p[0], fmaxf(p[1], p[2]));
        float e0 = expf(p[0] - m), e1 = expf(p[1] - m), e2 = expf(p[2] - m);
        float inv = 1.f / (e0 + e1 + e2);
        g_beta[4] = e0 * inv;
        g_beta[5] = e1 * inv;
        g_beta[6] = e2 * inv;
    }
}

__global__ void final_kernel(const float *__restrict__ tf, float *__restrict__ out, int n) {
    int i = blockIdx.x * blockDim.x + threadIdx.x;
    if (i >= n * 32) return;
    float b0 = g_beta[4], b1 = g_beta[5], b2 = g_beta[6];
    float2 e0 = ((const float2 *)g_E0)[i];
    float2 e1 = ((const float2 *)g_E1)[i];
    float2 t = ((const float2 *)tf)[i];
    float2 o;
    o.x = b0 * e0.x + b1 * e1.x + b2 * t.x;
    o.y = b0 * e0.y + b1 * e1.y + b2 * t.y;
    ((float2 *)out)[i] = o;
}

// ---------------- launch ----------------
extern "C" void kernel_launch(void *const *d_in, const int *in_sizes, int n_in,
                              void *d_out, int out_size) {
    const float *tf = (const float *)d_in[0];
    const float *h0 = (const float *)d_in[1];
    const float *h1 = (const float *)d_in[2];
    const float *h2 = (const float *)d_in[3];
    const float *rf0 = (const float *)d_in[4];
    const float *rf1 = (const float *)d_in[5];
    const float *rf2 = (const float *)d_in[6];
    const int *nei0 = (const int *)d_in[7];
    const int *nei1 = (const int *)d_in[8];
    const float *att0 = (const float *)d_in[9];
    const float *att2_0 = (const float *)d_in[10];
    const float *Wr0 = (const float *)d_in[11];
    const float *br0 = (const float *)d_in[12];
    const float *Wr2_0 = (const float *)d_in[13];
    const float *br2_0 = (const float *)d_in[14];
    const float *aggW0 = (const float *)d_in[15];
    const float *aggb0 = (const float *)d_in[16];
    const float *aggatt0 = (const float *)d_in[17];
    const float *att1 = (const float *)d_in[18];
    const float *att2_1 = (const float *)d_in[19];
    const float *Wr1 = (const float *)d_in[20];
    const float *br1 = (const float *)d_in[21];
    const float *Wr2_1 = (const float *)d_in[22];
    const float *br2_1 = (const float *)d_in[23];
    const float *aggW1 = (const float *)d_in[24];
    const float *aggb1 = (const float *)d_in[25];
    const float *aggatt1 = (const float *)d_in[26];
    const float *interW = (const float *)d_in[27];
    const float *interb = (const float *)d_in[28];
    const float *interatt = (const float *)d_in[29];

    int n = in_sizes[0] / 64;
    if (n > NMAX) n = NMAX;
    int m1 = in_sizes[2] / 64; if (m1 > M1MAX) m1 = M1MAX;
    int m2 = in_sizes[3] / 64; if (m2 > M2MAX) m2 = M2MAX;
    float *out = (float *)d_out;

    static const size_t PREP_SMEM = (size_t)PREP_SMEM_F * 4;
    static const size_t GEMV_SMEM = (size_t)GEMV_SMEM_F * 4;
    cudaFuncSetAttribute(prep_v2, cudaFuncAttributeMaxDynamicSharedMemorySize, (int)PREP_SMEM);
    cudaFuncSetAttribute(gemv_tanh_sum_v2, cudaFuncAttributeMaxDynamicSharedMemorySize, (int)GEMV_SMEM);

    // device pointers for the __device__ scratch float2 tables
    float2 *cd_t1, *cd_r1, *cd_t2, *cd_r2;
    cudaGetSymbolAddress((void **)&cd_t1, g_cd_t1);
    cudaGetSymbolAddress((void **)&cd_r1, g_cd_r1);
    cudaGetSymbolAddress((void **)&cd_t2, g_cd_t2);
    cudaGetSymbolAddress((void **)&cd_r2, g_cd_r2);

    init_kernel<<<1, 512>>>();

    // per-row table precompute (dot with att[64:], L1)
    precomp_kernel<<<(m1 + 7) / 8, 256>>>(h1, rf1, cd_t1, cd_r1, att0 + 64, att2_0 + 64, m1);
    precomp_kernel<<<(m2 + 7) / 8, 256>>>(h2, rf2, cd_t2, cd_r2, att1 + 64, att2_1 + 64, m2);

    int tblocks = (n + 255) / 256;
    // prep: c_ref / L1(refp) for the 4 branches
    prep_v2<<<tblocks, 256, PREP_SMEM>>>(h0, Wr0, br0, att0, Wr1, br1, att1, 0, 2, n);
    prep_v2<<<tblocks, 256, PREP_SMEM>>>(rf0, Wr2_0, br2_0, att2_0, Wr2_1, br2_1, att2_1, 1, 3, n);

    int ablocks = (n + 7) / 8;
    attn_v2<<<ablocks, 256>>>(h1, rf1, nei0, cd_t1, cd_r1, 0, n);
    attn_v2<<<ablocks, 256>>>(h2, rf2, nei1, cd_t2, cd_r2, 2, n);

    // semantic-agg tanh column sums (4 branches) + inter tanh sum of target
    gemv_tanh_sum_v2<<<tblocks, 256, GEMV_SMEM>>>(nullptr, 0, aggW0, aggb0, 0, n);
    gemv_tanh_sum_v2<<<tblocks, 256, GEMV_SMEM>>>(nullptr, 1, aggW0, aggb0, 1, n);
    gemv_tanh_sum_v2<<<tblocks, 256, GEMV_SMEM>>>(nullptr, 2, aggW1, aggb1, 2, n);
    gemv_tanh_sum_v2<<<tblocks, 256, GEMV_SMEM>>>(nullptr, 3, aggW1, aggb1, 3, n);
    gemv_tanh_sum_v2<<<tblocks, 256, GEMV_SMEM>>>(tf, -1, interW, interb, 6, n);

    beta_rel_kernel<<<1, 64>>>(aggatt0, aggatt1, n);

    int eblocks = (n * 32 + 255) / 256;
    combine_kernel<<<eblocks, 256>>>(n);

    // inter tanh column sums for the two combined embeddings
    gemv_tanh_sum_v2<<<tblocks, 256, GEMV_SMEM>>>(nullptr, 4, interW, interb, 4, n);
    gemv_tanh_sum_v2<<<tblocks, 256, GEMV_SMEM>>>(nullptr, 5, interW, interb, 5, n);

    beta_inter_kernel<<<1, 32>>>(interatt, n);

    final_kernel<<<eblocks, 256>>>(tf, out, n);
}